// round 3
// baseline (speedup 1.0000x reference)
#include <cuda_runtime.h>
#include <mma.h>
#include <math.h>
#include <stdint.h>

using namespace nvcuda;

#define BATCH   4096
#define DDIM    1024
#define NKB     65536
#define NSPLIT  8
#define KBSPLIT (NKB / NSPLIT)
#define TOPK    32
#define OUTW    3072

// ---------------- scratch (static device globals; no allocations) ----------
__device__ float g_q[BATCH * DDIM];             // q = C @ Q^T (fp32)
__device__ float g_qsq[BATCH];                  // ||q_i||^2
__device__ float g_kbsq[NKB];                   // ||kb_j||^2
__device__ float g_pd[BATCH * NSPLIT * TOPK];   // partial top-k d2
__device__ int   g_pi[BATCH * NSPLIT * TOPK];   // partial top-k indices

__device__ __forceinline__ float f_inf() { return __int_as_float(0x7f800000); }

// Stage a 128x32 fp32 tile into shared as tf32, row stride 36 (pad for banks).
__device__ __forceinline__ void stage128x32(float* dst, const float* __restrict__ src,
                                            int row_base, int kk, int tid) {
#pragma unroll
    for (int i = 0; i < 4; i++) {
        int e   = tid + i * 256;   // 1024 float4 slots
        int row = e >> 3;          // 8 float4 per row
        int c4  = e & 7;
        float4 v = *reinterpret_cast<const float4*>(
            src + (size_t)(row_base + row) * DDIM + kk + c4 * 4);
        float4 w;
        w.x = wmma::__float_to_tf32(v.x);
        w.y = wmma::__float_to_tf32(v.y);
        w.z = wmma::__float_to_tf32(v.z);
        w.w = wmma::__float_to_tf32(v.w);
        *reinterpret_cast<float4*>(dst + row * 36 + c4 * 4) = w;
    }
}

// ---------------- K1: q = C @ Q^T  (tf32 wmma, 128x128 tiles) ---------------
__global__ __launch_bounds__(256) void qgemm_kernel(const float* __restrict__ Cm,
                                                    const float* __restrict__ Qw) {
    extern __shared__ float sm[];
    float* As = sm;                 // 128x36
    float* Bs = sm + 128 * 36;      // 128x36
    int tid  = threadIdx.x;
    int warp = tid >> 5, wm = warp >> 1, wn = warp & 1;
    int mbase = blockIdx.y * 128;
    int nbase = blockIdx.x * 128;

    wmma::fragment<wmma::accumulator, 16, 16, 8, float> fc[2][4];
#pragma unroll
    for (int i = 0; i < 2; i++)
#pragma unroll
        for (int j = 0; j < 4; j++) wmma::fill_fragment(fc[i][j], 0.0f);

    for (int kk = 0; kk < DDIM; kk += 32) {
        stage128x32(As, Cm, mbase, kk, tid);
        stage128x32(Bs, Qw, nbase, kk, tid);
        __syncthreads();
#pragma unroll
        for (int ks = 0; ks < 4; ks++) {
            wmma::fragment<wmma::matrix_a, 16, 16, 8, wmma::precision::tf32, wmma::row_major> fa0, fa1;
            wmma::load_matrix_sync(fa0, As + (wm * 32) * 36 + ks * 8, 36);
            wmma::load_matrix_sync(fa1, As + (wm * 32 + 16) * 36 + ks * 8, 36);
#pragma unroll
            for (int j = 0; j < 4; j++) {
                wmma::fragment<wmma::matrix_b, 16, 16, 8, wmma::precision::tf32, wmma::col_major> fb;
                wmma::load_matrix_sync(fb, Bs + (wn * 64 + j * 16) * 36 + ks * 8, 36);
                wmma::mma_sync(fc[0][j], fa0, fb, fc[0][j]);
                wmma::mma_sync(fc[1][j], fa1, fb, fc[1][j]);
            }
        }
        __syncthreads();
    }
#pragma unroll
    for (int i = 0; i < 2; i++)
#pragma unroll
        for (int j = 0; j < 4; j++) {
            float* dst = g_q + (size_t)(mbase + wm * 32 + i * 16) * DDIM
                             + nbase + wn * 64 + j * 16;
            wmma::store_matrix_sync(dst, fc[i][j], DDIM, wmma::mem_row_major);
        }
}

// ---------------- K2: row sums of squares (q and kb) ------------------------
__global__ __launch_bounds__(256) void rowsq_kernel(const float* __restrict__ kb) {
    int warp = threadIdx.x >> 5, lane = threadIdx.x & 31;
    int row = blockIdx.x * 8 + warp;
    const float* src;
    float* dst;
    if (row < BATCH) {
        src = g_q + (size_t)row * DDIM;
        dst = &g_qsq[row];
    } else {
        int r2 = row - BATCH;
        if (r2 >= NKB) return;
        src = kb + (size_t)r2 * DDIM;
        dst = &g_kbsq[r2];
    }
    const float4* p = reinterpret_cast<const float4*>(src);
    float s = 0.f;
#pragma unroll
    for (int i = 0; i < 8; i++) {
        float4 v = p[lane + i * 32];
        s += v.x * v.x + v.y * v.y + v.z * v.z + v.w * v.w;
    }
#pragma unroll
    for (int o = 16; o; o >>= 1) s += __shfl_xor_sync(0xffffffffu, s, o);
    if (lane == 0) *dst = s;
}

// ---------------- K3: fused distance GEMM + streaming top-32 ----------------
// grid: (BATCH/128 q-tiles, NSPLIT kb-splits). Each CTA: 128 queries vs 8192 kb rows.
__global__ __launch_bounds__(256) void dist_topk_kernel(const float* __restrict__ kb) {
    extern __shared__ float sm[];
    float* As   = sm;                      // 128x36
    float* Bs   = As + 128 * 36;           // 128x36
    float* Ds   = Bs + 128 * 36;           // 128x132 dot tile
    float* skb  = Ds + 128 * 132;          // 128 kb_sq
    float* topd = skb + 128;               // 128x33
    int*   topi = (int*)(topd + 128 * 33); // 128x33

    int tid  = threadIdx.x;
    int warp = tid >> 5, wm = warp >> 1, wn = warp & 1;
    int mbase = blockIdx.x * 128;
    int split = blockIdx.y;

    float qs = 0.f;
    float rmax = f_inf();
    int   rpos = 0;
    if (tid < 128) {
        qs = g_qsq[mbase + tid];
#pragma unroll
        for (int k = 0; k < TOPK; k++) topd[tid * 33 + k] = f_inf();
    }

    for (int nt = 0; nt < KBSPLIT / 128; nt++) {
        int nbase = split * KBSPLIT + nt * 128;

        wmma::fragment<wmma::accumulator, 16, 16, 8, float> fc[2][4];
#pragma unroll
        for (int i = 0; i < 2; i++)
#pragma unroll
            for (int j = 0; j < 4; j++) wmma::fill_fragment(fc[i][j], 0.0f);

        for (int kk = 0; kk < DDIM; kk += 32) {
            stage128x32(As, g_q, mbase, kk, tid);
            stage128x32(Bs, kb, nbase, kk, tid);
            __syncthreads();
#pragma unroll
            for (int ks = 0; ks < 4; ks++) {
                wmma::fragment<wmma::matrix_a, 16, 16, 8, wmma::precision::tf32, wmma::row_major> fa0, fa1;
                wmma::load_matrix_sync(fa0, As + (wm * 32) * 36 + ks * 8, 36);
                wmma::load_matrix_sync(fa1, As + (wm * 32 + 16) * 36 + ks * 8, 36);
#pragma unroll
                for (int j = 0; j < 4; j++) {
                    wmma::fragment<wmma::matrix_b, 16, 16, 8, wmma::precision::tf32, wmma::col_major> fb;
                    wmma::load_matrix_sync(fb, Bs + (wn * 64 + j * 16) * 36 + ks * 8, 36);
                    wmma::mma_sync(fc[0][j], fa0, fb, fc[0][j]);
                    wmma::mma_sync(fc[1][j], fa1, fb, fc[1][j]);
                }
            }
            __syncthreads();
        }

        // dot tile -> shared
#pragma unroll
        for (int i = 0; i < 2; i++)
#pragma unroll
            for (int j = 0; j < 4; j++)
                wmma::store_matrix_sync(Ds + (wm * 32 + i * 16) * 132 + wn * 64 + j * 16,
                                        fc[i][j], 132, wmma::mem_row_major);
        if (tid < 128) skb[tid] = g_kbsq[nbase + tid];
        __syncthreads();

        // per-row threshold-filtered top-32 insertion (1 thread per query row)
        if (tid < 128) {
            float* myd = topd + tid * 33;
            int*   myi = topi + tid * 33;
            const float* drow = Ds + tid * 132;
            for (int j = 0; j < 128; j++) {
                float d2 = qs + skb[j] - 2.0f * drow[j];
                if (d2 < rmax) {
                    myd[rpos] = d2;
                    myi[rpos] = nbase + j;
                    float m = -3.4e38f;
                    int p = 0;
#pragma unroll
                    for (int k = 0; k < TOPK; k++) {
                        float v = myd[k];
                        if (v > m) { m = v; p = k; }
                    }
                    rmax = m;
                    rpos = p;
                }
            }
        }
        __syncthreads();
    }

    if (tid < 128) {
#pragma unroll
        for (int k = 0; k < TOPK; k++) {
            size_t o = ((size_t)(mbase + tid) * NSPLIT + split) * TOPK + k;
            g_pd[o] = topd[tid * 33 + k];
            g_pi[o] = topi[tid * 33 + k];
        }
    }
}

// ---------------- K4: merge splits, softmax, gather, SiLU epilogue ----------
__device__ __forceinline__ float silu_f(float x) { return x / (1.0f + expf(-x)); }

__global__ __launch_bounds__(256) void merge_kernel(const float* __restrict__ kb,
                                                    const float* __restrict__ Cm,
                                                    const float* __restrict__ Km,
                                                    const float* __restrict__ temp_p,
                                                    float* __restrict__ out) {
    __shared__ float cd[256];
    __shared__ int   ci[256];
    __shared__ float sv[256];
    __shared__ int   sp[256];
    __shared__ float sd[TOPK];
    __shared__ int   si[TOPK];
    __shared__ float sw[TOPK];

    int q = blockIdx.x;
    int tid = threadIdx.x;

    cd[tid] = g_pd[(size_t)q * NSPLIT * TOPK + tid];
    ci[tid] = g_pi[(size_t)q * NSPLIT * TOPK + tid];
    __syncthreads();

    // select 32 smallest of 256 candidates via repeated argmin
    for (int s = 0; s < TOPK; s++) {
        sv[tid] = cd[tid];
        sp[tid] = tid;
        __syncthreads();
#pragma unroll
        for (int off = 128; off; off >>= 1) {
            if (tid < off && sv[tid + off] < sv[tid]) {
                sv[tid] = sv[tid + off];
                sp[tid] = sp[tid + off];
            }
            __syncthreads();
        }
        if (tid == 0) {
            int p = sp[0];
            sd[s] = cd[p];
            si[s] = ci[p];
            cd[p] = f_inf();
        }
        __syncthreads();
    }

    // softmax(-dist / temperature) over the 32 selected
    if (tid < TOPK) {
        float dist  = sqrtf(fmaxf(sd[tid], 0.0f));
        float logit = -dist / temp_p[0];
        float m = logit;
#pragma unroll
        for (int o = 16; o; o >>= 1) m = fmaxf(m, __shfl_xor_sync(0xffffffffu, m, o));
        float e = expf(logit - m);
        float ss = e;
#pragma unroll
        for (int o = 16; o; o >>= 1) ss += __shfl_xor_sync(0xffffffffu, ss, o);
        sw[tid] = e / ss;
    }
    __syncthreads();

    // T = sum_k w_k * kb[idx_k]  (each thread owns 4 contiguous cols)
    float4 acc = make_float4(0.f, 0.f, 0.f, 0.f);
#pragma unroll 4
    for (int k = 0; k < TOPK; k++) {
        float wk = sw[k];
        const float4* row = reinterpret_cast<const float4*>(kb + (size_t)si[k] * DDIM);
        float4 v = row[tid];
        acc.x += wk * v.x; acc.y += wk * v.y; acc.z += wk * v.z; acc.w += wk * v.w;
    }

    float4* o4 = reinterpret_cast<float4*>(out + (size_t)q * OUTW);
    const float4* c4 = reinterpret_cast<const float4*>(Cm + (size_t)q * DDIM);
    const float4* k4 = reinterpret_cast<const float4*>(Km + (size_t)q * DDIM);

    float4 cv = c4[tid], kv = k4[tid], r;
    r.x = silu_f(cv.x); r.y = silu_f(cv.y); r.z = silu_f(cv.z); r.w = silu_f(cv.w);
    o4[tid] = r;
    r.x = silu_f(0.5f * kv.x); r.y = silu_f(0.5f * kv.y);
    r.z = silu_f(0.5f * kv.z); r.w = silu_f(0.5f * kv.w);
    o4[256 + tid] = r;
    r.x = silu_f(0.25f * acc.x); r.y = silu_f(0.25f * acc.y);
    r.z = silu_f(0.25f * acc.z); r.w = silu_f(0.25f * acc.w);
    o4[512 + tid] = r;
}

// ---------------- launch -----------------------------------------------------
extern "C" void kernel_launch(void* const* d_in, const int* in_sizes, int n_in,
                              void* d_out, int out_size) {
    // size-based routing (C and K share a size -> order preserved)
    int iC = -1, iK = -1, iKB = -1, iQ = -1, iT = -1;
    for (int i = 0; i < n_in; i++) {
        int s = in_sizes[i];
        if (s == NKB * DDIM)            iKB = i;
        else if (s == DDIM * DDIM)      iQ = i;
        else if (s == BATCH * DDIM)     { if (iC < 0) iC = i; else iK = i; }
        else if (s == 1)                { if (iT < 0) iT = i; }
    }
    const float* C    = (const float*)d_in[iC];
    const float* Kin  = (const float*)d_in[iK];
    const float* kb   = (const float*)d_in[iKB];
    const float* Qw   = (const float*)d_in[iQ];
    const float* temp = (const float*)d_in[iT];
    float* out = (float*)d_out;

    const int k3_smem = (128 * 36 * 2 + 128 * 132 + 128 + 128 * 33) * 4 + 128 * 33 * 4;
    cudaFuncSetAttribute(dist_topk_kernel,
                         cudaFuncAttributeMaxDynamicSharedMemorySize, k3_smem);

    qgemm_kernel<<<dim3(DDIM / 128, BATCH / 128), 256, 2 * 128 * 36 * 4>>>(C, Qw);
    rowsq_kernel<<<(BATCH + NKB) / 8, 256>>>(kb);
    dist_topk_kernel<<<dim3(BATCH / 128, NSPLIT), 256, k3_smem>>>(kb);
    merge_kernel<<<BATCH, 256>>>(kb, C, Kin, temp, out);
}